// round 1
// baseline (speedup 1.0000x reference)
#include <cuda_runtime.h>
#include <cuda_bf16.h>
#include <math.h>
#include <stdint.h>

// ---------------- Problem constants (fixed shapes) ----------------
#define BATCH 2
#define SEQ   2048
#define NTOK  (BATCH*SEQ)        // 4096
#define HID   2048
#define NH    16
#define DQ    192                // 128 nope + 64 rope
#define DNOPE 128
#define DROPE 64
#define DV    128
#define KVR   512
#define INTER 10944

// ---------------- Scratch (device globals; allocation-free) ----------------
__device__ float g_xln [NTOK*HID];
__device__ float g_q   [NTOK*NH*DQ];
__device__ float g_ckv [NTOK*(KVR+DROPE)];
__device__ float g_cln [NTOK*KVR];
__device__ float g_kv  [NTOK*NH*(DNOPE+DV)];
__device__ float g_qf  [BATCH*NH*SEQ*DQ];
__device__ float g_kf  [BATCH*NH*SEQ*DQ];
__device__ float g_v   [BATCH*NH*SEQ*DV];
__device__ float g_attn[NTOK*HID];
__device__ float g_x1  [NTOK*HID];
__device__ float g_y   [NTOK*HID];
__device__ float g_g   [NTOK*INTER];
__device__ float g_u   [NTOK*INTER];

// ---------------- RMSNorm ----------------
__global__ void rmsnorm_kernel(const float* __restrict__ in, const float* __restrict__ w,
                               float* __restrict__ out, int cols, int instride) {
    int row = blockIdx.x;
    int tid = threadIdx.x;
    const float* xr = in + (size_t)row * instride;
    float s = 0.f;
    for (int c = tid; c < cols; c += 256) { float v = xr[c]; s += v * v; }
    __shared__ float red[8];
    for (int o = 16; o; o >>= 1) s += __shfl_xor_sync(0xffffffffu, s, o);
    if ((tid & 31) == 0) red[tid >> 5] = s;
    __syncthreads();
    float tot = 0.f;
    #pragma unroll
    for (int i = 0; i < 8; i++) tot += red[i];
    float inv = rsqrtf(tot / (float)cols + 1e-6f);
    for (int c = tid; c < cols; c += 256)
        out[(size_t)row * cols + c] = xr[c] * inv * w[c];
}

// ---------------- SGEMM: C[M,N] = A[M,K] @ W[N,K]^T (+R)  (NT, both K-major)
// 128x128 tile, BK=16, 256 threads, 8x8 per thread.
template<int EPI>  // 0: none, 1: add residual R[M,N]
__global__ void __launch_bounds__(256, 2)
sgemm_nt(const float* __restrict__ A, const float* __restrict__ W,
         const float* __restrict__ R, float* __restrict__ C,
         int M, int N, int K) {
    __shared__ float As[16][132];
    __shared__ float Ws[16][132];
    int tid = threadIdx.x;
    int bm = blockIdx.y * 128;
    int bn = blockIdx.x * 128;
    int tx = tid & 15, ty = tid >> 4;
    float acc[8][8];
    #pragma unroll
    for (int i = 0; i < 8; i++)
        #pragma unroll
        for (int j = 0; j < 8; j++) acc[i][j] = 0.f;

    int lr = tid >> 2;          // 0..63
    int lc = (tid & 3) * 4;     // 0,4,8,12

    for (int k0 = 0; k0 < K; k0 += 16) {
        #pragma unroll
        for (int i = 0; i < 2; i++) {
            int row = lr + 64 * i;
            float4 v = *(const float4*)&A[(size_t)(bm + row) * K + k0 + lc];
            As[lc + 0][row] = v.x; As[lc + 1][row] = v.y;
            As[lc + 2][row] = v.z; As[lc + 3][row] = v.w;
        }
        #pragma unroll
        for (int i = 0; i < 2; i++) {
            int row = lr + 64 * i;
            float4 v = make_float4(0.f, 0.f, 0.f, 0.f);
            if (bn + row < N) v = *(const float4*)&W[(size_t)(bn + row) * K + k0 + lc];
            Ws[lc + 0][row] = v.x; Ws[lc + 1][row] = v.y;
            Ws[lc + 2][row] = v.z; Ws[lc + 3][row] = v.w;
        }
        __syncthreads();
        #pragma unroll
        for (int kk = 0; kk < 16; kk++) {
            float a[8], b[8];
            #pragma unroll
            for (int i = 0; i < 8; i += 4) *(float4*)&a[i] = *(const float4*)&As[kk][ty * 8 + i];
            #pragma unroll
            for (int j = 0; j < 8; j += 4) *(float4*)&b[j] = *(const float4*)&Ws[kk][tx * 8 + j];
            #pragma unroll
            for (int i = 0; i < 8; i++)
                #pragma unroll
                for (int j = 0; j < 8; j++)
                    acc[i][j] += a[i] * b[j];
        }
        __syncthreads();
    }
    #pragma unroll
    for (int i = 0; i < 8; i++) {
        int row = bm + ty * 8 + i;
        #pragma unroll
        for (int j = 0; j < 8; j++) {
            int col = bn + tx * 8 + j;
            if (col < N) {
                float v = acc[i][j];
                if (EPI == 1) v += R[(size_t)row * N + col];
                C[(size_t)row * N + col] = v;
            }
        }
    }
}

// ---------------- RoPE (yarn) helpers ----------------
// inv_freq[j] = fi*ramp + fe*(1-ramp); fe = 10000^{-j/32}; fi = fe/40;
// ramp = clamp((j-10)/13, 0, 1).  mscale ratio = 1 (MSCALE==MSCALE_ALL).
__device__ __forceinline__ void yarn_cossin(int j, int pos, float& c, float& s) {
    float ar = (float)j * (1.0f / 32.0f);
    float fe = __powf(10000.0f, -ar);
    float fi = fe * (1.0f / 40.0f);
    float ramp = fminf(fmaxf(((float)j - 10.0f) * (1.0f / 13.0f), 0.0f), 1.0f);
    float f = fi * ramp + fe * (1.0f - ramp);
    float a = (float)pos * f;
    c = cosf(a); s = sinf(a);
}

// q [NTOK, NH*DQ] -> qf [B,H,S,DQ] with rope on last 64 (deinterleaved)
__global__ void build_qf(const float* __restrict__ q, const int* __restrict__ pos_ids,
                         float* __restrict__ qf) {
    int t = blockIdx.x;                 // token index b*SEQ+s
    int b = t / SEQ, s = t % SEQ;
    int tid = threadIdx.x;              // 128
    __shared__ float cs[32], sn[32];
    int pos = pos_ids[t];
    if (tid < 32) yarn_cossin(tid, pos, cs[tid], sn[tid]);
    __syncthreads();
    for (int h = 0; h < NH; h++) {
        size_t src = (size_t)t * (NH * DQ) + h * DQ;
        size_t dst = ((size_t)(b * NH + h) * SEQ + s) * DQ;
        qf[dst + tid] = q[src + tid];
        if (tid < 32) {
            float p0 = q[src + DNOPE + 2 * tid];
            float p1 = q[src + DNOPE + 2 * tid + 1];
            qf[dst + DNOPE + tid]      = p0 * cs[tid] - p1 * sn[tid];
            qf[dst + DNOPE + 32 + tid] = p1 * cs[tid] + p0 * sn[tid];
        }
    }
}

// kv [NTOK, NH*256], ckv [NTOK, 576] -> kf [B,H,S,192], v [B,H,S,128]
__global__ void build_kf(const float* __restrict__ kv, const float* __restrict__ ckv,
                         const int* __restrict__ pos_ids,
                         float* __restrict__ kf, float* __restrict__ vv) {
    int t = blockIdx.x;
    int b = t / SEQ, s = t % SEQ;
    int tid = threadIdx.x;              // 128
    __shared__ float cs[32], sn[32], kr[64];
    int pos = pos_ids[t];
    if (tid < 32) yarn_cossin(tid, pos, cs[tid], sn[tid]);
    __syncthreads();
    if (tid < 32) {
        float p0 = ckv[(size_t)t * (KVR + DROPE) + KVR + 2 * tid];
        float p1 = ckv[(size_t)t * (KVR + DROPE) + KVR + 2 * tid + 1];
        kr[tid]      = p0 * cs[tid] - p1 * sn[tid];
        kr[tid + 32] = p1 * cs[tid] + p0 * sn[tid];
    }
    __syncthreads();
    for (int h = 0; h < NH; h++) {
        size_t src = (size_t)t * (NH * 256) + h * 256;
        size_t d0 = ((size_t)(b * NH + h) * SEQ + s);
        kf[d0 * DQ + tid] = kv[src + tid];
        vv[d0 * DV + tid] = kv[src + DNOPE + tid];
        if (tid < 64) kf[d0 * DQ + DNOPE + tid] = kr[tid];
    }
}

// ---------------- Causal attention, online softmax ----------------
// grid (SEQ/16, NH, BATCH), 256 threads. Each block: 16 queries of one (b,h).
// thread (q16=tid/16, x16=tid%16): computes logit (q16, key x16) per 16-key
// chunk, then owns output dims [x16*8, x16*8+8) of query q16.
__global__ void __launch_bounds__(256)
attn_kernel(const float* __restrict__ qf, const float* __restrict__ kf,
            const float* __restrict__ vv, float* __restrict__ out) {
    __shared__ float qs[16][196];
    __shared__ float ks[16][196];
    __shared__ float vs[16][128];
    __shared__ float lg[16][16];
    int tid = threadIdx.x;
    int q16 = tid >> 4, x16 = tid & 15;
    int b = blockIdx.z, h = blockIdx.y;
    int q0 = blockIdx.x * 16;
    size_t bqk = (size_t)(b * NH + h) * SEQ * DQ;
    size_t bv  = (size_t)(b * NH + h) * SEQ * DV;

    for (int i = tid; i < 16 * 48; i += 256) {   // 16*192 floats as float4
        int r = i / 48, c4 = i % 48;
        *(float4*)&qs[r][c4 * 4] = *(const float4*)&qf[bqk + (size_t)(q0 + r) * DQ + c4 * 4];
    }
    float acc[8];
    #pragma unroll
    for (int j = 0; j < 8; j++) acc[j] = 0.f;
    float m = -INFINITY, l = 0.f;
    int myq = q0 + q16;
    const float scale = 0.07216878364870323f;    // 192^-0.5

    for (int kc = 0; kc < q0 + 16; kc += 16) {
        __syncthreads();
        for (int i = tid; i < 16 * 48; i += 256) {
            int r = i / 48, c4 = i % 48;
            *(float4*)&ks[r][c4 * 4] = *(const float4*)&kf[bqk + (size_t)(kc + r) * DQ + c4 * 4];
        }
        for (int i = tid; i < 16 * 32; i += 256) {
            int r = i / 32, c4 = i % 32;
            *(float4*)&vs[r][c4 * 4] = *(const float4*)&vv[bv + (size_t)(kc + r) * DV + c4 * 4];
        }
        __syncthreads();
        float dot = 0.f;
        #pragma unroll 8
        for (int d = 0; d < DQ; d += 4) {
            float4 a = *(const float4*)&qs[q16][d];
            float4 k4 = *(const float4*)&ks[x16][d];
            dot += a.x * k4.x + a.y * k4.y + a.z * k4.z + a.w * k4.w;
        }
        lg[q16][x16] = (kc + x16 <= myq) ? dot * scale : -INFINITY;
        __syncthreads();
        float cmax = -INFINITY;
        #pragma unroll
        for (int k = 0; k < 16; k++) cmax = fmaxf(cmax, lg[q16][k]);
        float nm = fmaxf(m, cmax);
        float corr = __expf(m - nm);
        l *= corr;
        #pragma unroll
        for (int j = 0; j < 8; j++) acc[j] *= corr;
        #pragma unroll
        for (int k = 0; k < 16; k++) {
            float p = __expf(lg[q16][k] - nm);
            l += p;
            const float* vr = &vs[k][x16 * 8];
            #pragma unroll
            for (int j = 0; j < 8; j++) acc[j] += p * vr[j];
        }
        m = nm;
    }
    float inv = 1.0f / l;
    size_t o = ((size_t)(b * SEQ + myq)) * (NH * DV) + h * DV + x16 * 8;
    #pragma unroll
    for (int j = 0; j < 8; j++) out[o + j] = acc[j] * inv;
}

// ---------------- SiLU(g)*u, in place into g ----------------
__global__ void silu_mul(float* __restrict__ g, const float* __restrict__ u, size_t n) {
    for (size_t i = (size_t)blockIdx.x * blockDim.x + threadIdx.x; i < n;
         i += (size_t)gridDim.x * blockDim.x) {
        float x = g[i];
        g[i] = x / (1.0f + __expf(-x)) * u[i];
    }
}

// ---------------- Launch ----------------
extern "C" void kernel_launch(void* const* d_in, const int* in_sizes, int n_in,
                              void* d_out, int out_size) {
    const float* hidden = (const float*)d_in[0];
    const int*   pos    = (const int*)d_in[1];
    const float* Wq     = (const float*)d_in[2];
    const float* Wkva   = (const float*)d_in[3];
    const float* w_kvln = (const float*)d_in[4];
    const float* Wkvb   = (const float*)d_in[5];
    const float* Wo     = (const float*)d_in[6];
    const float* Wg     = (const float*)d_in[7];
    const float* Wu     = (const float*)d_in[8];
    const float* Wd     = (const float*)d_in[9];
    const float* w_ln1  = (const float*)d_in[10];
    const float* w_ln2  = (const float*)d_in[11];
    float* out = (float*)d_out;

    float *xln, *q, *ckv, *cln, *kv, *qfp, *kfp, *vp, *attn, *x1, *y, *gg, *uu;
    cudaGetSymbolAddress((void**)&xln,  g_xln);
    cudaGetSymbolAddress((void**)&q,    g_q);
    cudaGetSymbolAddress((void**)&ckv,  g_ckv);
    cudaGetSymbolAddress((void**)&cln,  g_cln);
    cudaGetSymbolAddress((void**)&kv,   g_kv);
    cudaGetSymbolAddress((void**)&qfp,  g_qf);
    cudaGetSymbolAddress((void**)&kfp,  g_kf);
    cudaGetSymbolAddress((void**)&vp,   g_v);
    cudaGetSymbolAddress((void**)&attn, g_attn);
    cudaGetSymbolAddress((void**)&x1,   g_x1);
    cudaGetSymbolAddress((void**)&y,    g_y);
    cudaGetSymbolAddress((void**)&gg,   g_g);
    cudaGetSymbolAddress((void**)&uu,   g_u);

    dim3 blk(256);
    // 1. ln1
    rmsnorm_kernel<<<NTOK, blk>>>(hidden, w_ln1, xln, HID, HID);
    // 2. q = xln @ Wq^T   [4096 x 3072]
    sgemm_nt<0><<<dim3((NH * DQ + 127) / 128, NTOK / 128), blk>>>(xln, Wq, nullptr, q, NTOK, NH * DQ, HID);
    // 3. ckv = xln @ Wkva^T  [4096 x 576]
    sgemm_nt<0><<<dim3((KVR + DROPE + 127) / 128, NTOK / 128), blk>>>(xln, Wkva, nullptr, ckv, NTOK, KVR + DROPE, HID);
    // 4. c_ln = rms(ckv[:, :512]) * w_kvln
    rmsnorm_kernel<<<NTOK, blk>>>(ckv, w_kvln, cln, KVR, KVR + DROPE);
    // 5. kv = c_ln @ Wkvb^T  [4096 x 4096]
    sgemm_nt<0><<<dim3((NH * 256) / 128, NTOK / 128), blk>>>(cln, Wkvb, nullptr, kv, NTOK, NH * 256, KVR);
    // 6/7. layouts + rope
    build_qf<<<NTOK, 128>>>(q, pos, qfp);
    build_kf<<<NTOK, 128>>>(kv, ckv, pos, kfp, vp);
    // 8. attention
    attn_kernel<<<dim3(SEQ / 16, NH, BATCH), blk>>>(qfp, kfp, vp, attn);
    // 9. x1 = hidden + attn @ Wo^T
    sgemm_nt<1><<<dim3(HID / 128, NTOK / 128), blk>>>(attn, Wo, hidden, x1, NTOK, HID, NH * DV);
    // 10. y = rms(x1) * w_ln2
    rmsnorm_kernel<<<NTOK, blk>>>(x1, w_ln2, y, HID, HID);
    // 11. g = y @ Wg^T, u = y @ Wu^T  [4096 x 10944]
    sgemm_nt<0><<<dim3((INTER + 127) / 128, NTOK / 128), blk>>>(y, Wg, nullptr, gg, NTOK, INTER, HID);
    sgemm_nt<0><<<dim3((INTER + 127) / 128, NTOK / 128), blk>>>(y, Wu, nullptr, uu, NTOK, INTER, HID);
    // 12. g = silu(g) * u
    silu_mul<<<4096, blk>>>(gg, uu, (size_t)NTOK * INTER);
    // 13. out = x1 + g @ Wd^T
    sgemm_nt<1><<<dim3(HID / 128, NTOK / 128), blk>>>(gg, Wd, x1, out, NTOK, HID, INTER);
}

// round 3
// speedup vs baseline: 2.0334x; 2.0334x over previous
#include <cuda_runtime.h>
#include <cuda_bf16.h>
#include <math.h>
#include <stdint.h>

// ---------------- Problem constants (fixed shapes) ----------------
#define BATCH 2
#define SEQ   2048
#define NTOK  (BATCH*SEQ)        // 4096
#define HID   2048
#define NH    16
#define DQ    192                // 128 nope + 64 rope
#define DNOPE 128
#define DROPE 64
#define DV    128
#define KVR   512
#define INTER 10944

// ---------------- Scratch (device globals; allocation-free) ----------------
__device__ float g_xln [NTOK*HID];
__device__ float g_q   [NTOK*NH*DQ];
__device__ float g_ckv [NTOK*(KVR+DROPE)];
__device__ float g_cln [NTOK*KVR];
__device__ float g_kv  [NTOK*NH*(DNOPE+DV)];
__device__ float g_qf  [BATCH*NH*SEQ*DQ];
__device__ float g_kf  [BATCH*NH*SEQ*DQ];
__device__ float g_v   [BATCH*NH*SEQ*DV];
__device__ float g_attn[NTOK*HID];
__device__ float g_x1  [NTOK*HID];
__device__ float g_y   [NTOK*HID];
__device__ float g_g   [NTOK*INTER];
__device__ float g_u   [NTOK*INTER];

// ---------------- RMSNorm ----------------
__global__ void rmsnorm_kernel(const float* __restrict__ in, const float* __restrict__ w,
                               float* __restrict__ out, int cols, int instride) {
    int row = blockIdx.x;
    int tid = threadIdx.x;
    const float* xr = in + (size_t)row * instride;
    float s = 0.f;
    for (int c = tid; c < cols; c += 256) { float v = xr[c]; s += v * v; }
    __shared__ float red[8];
    for (int o = 16; o; o >>= 1) s += __shfl_xor_sync(0xffffffffu, s, o);
    if ((tid & 31) == 0) red[tid >> 5] = s;
    __syncthreads();
    float tot = 0.f;
    #pragma unroll
    for (int i = 0; i < 8; i++) tot += red[i];
    float inv = rsqrtf(tot / (float)cols + 1e-6f);
    for (int c = tid; c < cols; c += 256)
        out[(size_t)row * cols + c] = xr[c] * inv * w[c];
}

// ---------------- tf32 round helper ----------------
__device__ __forceinline__ float f2tf32(float x) {
    asm("cvt.rna.tf32.f32 %0, %0;" : "+f"(x));
    return x;
}

// ---------------- TF32 tensor-core GEMM ----------------
// C[M,N] = A[M,K] @ W[N,K]^T (+R). Both operands K-major (NT).
// CTA tile 128x128, BK=32. 256 threads = 8 warps (2m x 4n), warp tile 64x32.
// mma.sync.aligned.m16n8k8.row.col.f32.tf32.tf32.f32, rna-rounded operands.
// Requirements: M % 128 == 0, K % 32 == 0, N arbitrary (guarded).
template<int EPI>   // 0: none, 1: add residual R[M,N]
__global__ void __launch_bounds__(256, 2)
tf32gemm_nt(const float* __restrict__ A, const float* __restrict__ W,
            const float* __restrict__ R, float* __restrict__ C,
            int M, int N, int K) {
    __shared__ float As[128][36];   // [m][k], pitch 36 -> conflict-free frag loads
    __shared__ float Ws[128][36];   // [n][k]

    int tid  = threadIdx.x;
    int warp = tid >> 5, lane = tid & 31;
    int wm = warp >> 2;             // 0..1 : 64 rows
    int wn = warp & 3;              // 0..3 : 32 cols
    int g = lane >> 2, t = lane & 3;

    int bm = blockIdx.y * 128;
    int bn = blockIdx.x * 128;

    float acc[4][4][4];
    #pragma unroll
    for (int i = 0; i < 4; i++)
        #pragma unroll
        for (int j = 0; j < 4; j++)
            #pragma unroll
            for (int c = 0; c < 4; c++) acc[i][j][c] = 0.f;

    for (int k0 = 0; k0 < K; k0 += 32) {
        // ---- global -> smem (with rna tf32 rounding) ----
        #pragma unroll
        for (int i = 0; i < 4; i++) {
            int idx = tid + 256 * i;          // 0..1023
            int m   = idx >> 3;               // 0..127
            int c4  = (idx & 7) * 4;          // 0..28
            float4 v = *(const float4*)&A[(size_t)(bm + m) * K + k0 + c4];
            As[m][c4 + 0] = f2tf32(v.x); As[m][c4 + 1] = f2tf32(v.y);
            As[m][c4 + 2] = f2tf32(v.z); As[m][c4 + 3] = f2tf32(v.w);
        }
        #pragma unroll
        for (int i = 0; i < 4; i++) {
            int idx = tid + 256 * i;
            int n   = idx >> 3;
            int c4  = (idx & 7) * 4;
            float4 v = make_float4(0.f, 0.f, 0.f, 0.f);
            if (bn + n < N) v = *(const float4*)&W[(size_t)(bn + n) * K + k0 + c4];
            Ws[n][c4 + 0] = f2tf32(v.x); Ws[n][c4 + 1] = f2tf32(v.y);
            Ws[n][c4 + 2] = f2tf32(v.z); Ws[n][c4 + 3] = f2tf32(v.w);
        }
        __syncthreads();

        // ---- 4 k-steps of m16n8k8 ----
        #pragma unroll
        for (int ks = 0; ks < 4; ks++) {
            int kk = ks * 8;
            uint32_t af[4][4];
            #pragma unroll
            for (int i = 0; i < 4; i++) {
                int r = wm * 64 + i * 16 + g;
                af[i][0] = __float_as_uint(As[r    ][kk + t    ]);
                af[i][1] = __float_as_uint(As[r + 8][kk + t    ]);
                af[i][2] = __float_as_uint(As[r    ][kk + t + 4]);
                af[i][3] = __float_as_uint(As[r + 8][kk + t + 4]);
            }
            uint32_t bf[4][2];
            #pragma unroll
            for (int j = 0; j < 4; j++) {
                int n = wn * 32 + j * 8 + g;
                bf[j][0] = __float_as_uint(Ws[n][kk + t    ]);
                bf[j][1] = __float_as_uint(Ws[n][kk + t + 4]);
            }
            #pragma unroll
            for (int i = 0; i < 4; i++)
                #pragma unroll
                for (int j = 0; j < 4; j++) {
                    asm volatile(
                        "mma.sync.aligned.m16n8k8.row.col.f32.tf32.tf32.f32 "
                        "{%0,%1,%2,%3}, {%4,%5,%6,%7}, {%8,%9}, {%0,%1,%2,%3};"
                        : "+f"(acc[i][j][0]), "+f"(acc[i][j][1]),
                          "+f"(acc[i][j][2]), "+f"(acc[i][j][3])
                        : "r"(af[i][0]), "r"(af[i][1]), "r"(af[i][2]), "r"(af[i][3]),
                          "r"(bf[j][0]), "r"(bf[j][1]));
                }
        }
        __syncthreads();
    }

    // ---- epilogue ----
    #pragma unroll
    for (int i = 0; i < 4; i++) {
        int r0 = bm + wm * 64 + i * 16 + g;
        #pragma unroll
        for (int j = 0; j < 4; j++) {
            int c = bn + wn * 32 + j * 8 + 2 * t;
            if (c < N) {
                float2 v0 = make_float2(acc[i][j][0], acc[i][j][1]);
                float2 v1 = make_float2(acc[i][j][2], acc[i][j][3]);
                if (EPI == 1) {
                    float2 r = *(const float2*)&R[(size_t)r0 * N + c];
                    v0.x += r.x; v0.y += r.y;
                    float2 r2 = *(const float2*)&R[(size_t)(r0 + 8) * N + c];
                    v1.x += r2.x; v1.y += r2.y;
                }
                *(float2*)&C[(size_t)r0 * N + c]       = v0;
                *(float2*)&C[(size_t)(r0 + 8) * N + c] = v1;
            }
        }
    }
}

// ---------------- RoPE (yarn) helpers ----------------
__device__ __forceinline__ void yarn_cossin(int j, int pos, float& c, float& s) {
    float ar = (float)j * (1.0f / 32.0f);
    float fe = __powf(10000.0f, -ar);
    float fi = fe * (1.0f / 40.0f);
    float ramp = fminf(fmaxf(((float)j - 10.0f) * (1.0f / 13.0f), 0.0f), 1.0f);
    float f = fi * ramp + fe * (1.0f - ramp);
    float a = (float)pos * f;
    c = cosf(a); s = sinf(a);
}

// q [NTOK, NH*DQ] -> qf [B,H,S,DQ] with rope on last 64 (deinterleaved)
__global__ void build_qf(const float* __restrict__ q, const int* __restrict__ pos_ids,
                         float* __restrict__ qf) {
    int t = blockIdx.x;
    int b = t / SEQ, s = t % SEQ;
    int tid = threadIdx.x;              // 128
    __shared__ float cs[32], sn[32];
    int pos = pos_ids[t];
    if (tid < 32) yarn_cossin(tid, pos, cs[tid], sn[tid]);
    __syncthreads();
    for (int h = 0; h < NH; h++) {
        size_t src = (size_t)t * (NH * DQ) + h * DQ;
        size_t dst = ((size_t)(b * NH + h) * SEQ + s) * DQ;
        qf[dst + tid] = q[src + tid];
        if (tid < 32) {
            float p0 = q[src + DNOPE + 2 * tid];
            float p1 = q[src + DNOPE + 2 * tid + 1];
            qf[dst + DNOPE + tid]      = p0 * cs[tid] - p1 * sn[tid];
            qf[dst + DNOPE + 32 + tid] = p1 * cs[tid] + p0 * sn[tid];
        }
    }
}

// kv [NTOK, NH*256], ckv [NTOK, 576] -> kf [B,H,S,192], v [B,H,S,128]
__global__ void build_kf(const float* __restrict__ kv, const float* __restrict__ ckv,
                         const int* __restrict__ pos_ids,
                         float* __restrict__ kf, float* __restrict__ vv) {
    int t = blockIdx.x;
    int b = t / SEQ, s = t % SEQ;
    int tid = threadIdx.x;              // 128
    __shared__ float cs[32], sn[32], kr[64];
    int pos = pos_ids[t];
    if (tid < 32) yarn_cossin(tid, pos, cs[tid], sn[tid]);
    __syncthreads();
    if (tid < 32) {
        float p0 = ckv[(size_t)t * (KVR + DROPE) + KVR + 2 * tid];
        float p1 = ckv[(size_t)t * (KVR + DROPE) + KVR + 2 * tid + 1];
        kr[tid]      = p0 * cs[tid] - p1 * sn[tid];
        kr[tid + 32] = p1 * cs[tid] + p0 * sn[tid];
    }
    __syncthreads();
    for (int h = 0; h < NH; h++) {
        size_t src = (size_t)t * (NH * 256) + h * 256;
        size_t d0 = ((size_t)(b * NH + h) * SEQ + s);
        kf[d0 * DQ + tid] = kv[src + tid];
        vv[d0 * DV + tid] = kv[src + DNOPE + tid];
        if (tid < 64) kf[d0 * DQ + DNOPE + tid] = kr[tid];
    }
}

// ---------------- Causal attention, online softmax ----------------
__global__ void __launch_bounds__(256)
attn_kernel(const float* __restrict__ qf, const float* __restrict__ kf,
            const float* __restrict__ vv, float* __restrict__ out) {
    __shared__ float qs[16][196];
    __shared__ float ks[16][196];
    __shared__ float vs[16][128];
    __shared__ float lg[16][16];
    int tid = threadIdx.x;
    int q16 = tid >> 4, x16 = tid & 15;
    int b = blockIdx.z, h = blockIdx.y;
    int q0 = blockIdx.x * 16;
    size_t bqk = (size_t)(b * NH + h) * SEQ * DQ;
    size_t bv  = (size_t)(b * NH + h) * SEQ * DV;

    for (int i = tid; i < 16 * 48; i += 256) {
        int r = i / 48, c4 = i % 48;
        *(float4*)&qs[r][c4 * 4] = *(const float4*)&qf[bqk + (size_t)(q0 + r) * DQ + c4 * 4];
    }
    float acc[8];
    #pragma unroll
    for (int j = 0; j < 8; j++) acc[j] = 0.f;
    float m = -INFINITY, l = 0.f;
    int myq = q0 + q16;
    const float scale = 0.07216878364870323f;    // 192^-0.5

    for (int kc = 0; kc < q0 + 16; kc += 16) {
        __syncthreads();
        for (int i = tid; i < 16 * 48; i += 256) {
            int r = i / 48, c4 = i % 48;
            *(float4*)&ks[r][c4 * 4] = *(const float4*)&kf[bqk + (size_t)(kc + r) * DQ + c4 * 4];
        }
        for (int i = tid; i < 16 * 32; i += 256) {
            int r = i / 32, c4 = i % 32;
            *(float4*)&vs[r][c4 * 4] = *(const float4*)&vv[bv + (size_t)(kc + r) * DV + c4 * 4];
        }
        __syncthreads();
        float dot = 0.f;
        #pragma unroll 8
        for (int d = 0; d < DQ; d += 4) {
            float4 a = *(const float4*)&qs[q16][d];
            float4 k4 = *(const float4*)&ks[x16][d];
            dot += a.x * k4.x + a.y * k4.y + a.z * k4.z + a.w * k4.w;
        }
        lg[q16][x16] = (kc + x16 <= myq) ? dot * scale : -INFINITY;
        __syncthreads();
        float cmax = -INFINITY;
        #pragma unroll
        for (int k = 0; k < 16; k++) cmax = fmaxf(cmax, lg[q16][k]);
        float nm = fmaxf(m, cmax);
        float corr = __expf(m - nm);
        l *= corr;
        #pragma unroll
        for (int j = 0; j < 8; j++) acc[j] *= corr;
        #pragma unroll
        for (int k = 0; k < 16; k++) {
            float p = __expf(lg[q16][k] - nm);
            l += p;
            const float* vr = &vs[k][x16 * 8];
            #pragma unroll
            for (int j = 0; j < 8; j++) acc[j] += p * vr[j];
        }
        m = nm;
    }
    float inv = 1.0f / l;
    size_t o = ((size_t)(b * SEQ + myq)) * (NH * DV) + h * DV + x16 * 8;
    #pragma unroll
    for (int j = 0; j < 8; j++) out[o + j] = acc[j] * inv;
}

// ---------------- SiLU(g)*u, in place into g ----------------
__global__ void silu_mul(float* __restrict__ g, const float* __restrict__ u, size_t n) {
    for (size_t i = (size_t)blockIdx.x * blockDim.x + threadIdx.x; i < n;
         i += (size_t)gridDim.x * blockDim.x) {
        float x = g[i];
        g[i] = x / (1.0f + __expf(-x)) * u[i];
    }
}

// ---------------- Launch ----------------
extern "C" void kernel_launch(void* const* d_in, const int* in_sizes, int n_in,
                              void* d_out, int out_size) {
    const float* hidden = (const float*)d_in[0];
    const int*   pos    = (const int*)d_in[1];
    const float* Wq     = (const float*)d_in[2];
    const float* Wkva   = (const float*)d_in[3];
    const float* w_kvln = (const float*)d_in[4];
    const float* Wkvb   = (const float*)d_in[5];
    const float* Wo     = (const float*)d_in[6];
    const float* Wg     = (const float*)d_in[7];
    const float* Wu     = (const float*)d_in[8];
    const float* Wd     = (const float*)d_in[9];
    const float* w_ln1  = (const float*)d_in[10];
    const float* w_ln2  = (const float*)d_in[11];
    float* out = (float*)d_out;

    float *xln, *q, *ckv, *cln, *kv, *qfp, *kfp, *vp, *attn, *x1, *y, *gg, *uu;
    cudaGetSymbolAddress((void**)&xln,  g_xln);
    cudaGetSymbolAddress((void**)&q,    g_q);
    cudaGetSymbolAddress((void**)&ckv,  g_ckv);
    cudaGetSymbolAddress((void**)&cln,  g_cln);
    cudaGetSymbolAddress((void**)&kv,   g_kv);
    cudaGetSymbolAddress((void**)&qfp,  g_qf);
    cudaGetSymbolAddress((void**)&kfp,  g_kf);
    cudaGetSymbolAddress((void**)&vp,   g_v);
    cudaGetSymbolAddress((void**)&attn, g_attn);
    cudaGetSymbolAddress((void**)&x1,   g_x1);
    cudaGetSymbolAddress((void**)&y,    g_y);
    cudaGetSymbolAddress((void**)&gg,   g_g);
    cudaGetSymbolAddress((void**)&uu,   g_u);

    dim3 blk(256);
    // 1. ln1
    rmsnorm_kernel<<<NTOK, blk>>>(hidden, w_ln1, xln, HID, HID);
    // 2. q = xln @ Wq^T   [4096 x 3072] K=2048
    tf32gemm_nt<0><<<dim3((NH * DQ + 127) / 128, NTOK / 128), blk>>>(xln, Wq, nullptr, q, NTOK, NH * DQ, HID);
    // 3. ckv = xln @ Wkva^T  [4096 x 576] K=2048
    tf32gemm_nt<0><<<dim3((KVR + DROPE + 127) / 128, NTOK / 128), blk>>>(xln, Wkva, nullptr, ckv, NTOK, KVR + DROPE, HID);
    // 4. c_ln = rms(ckv[:, :512]) * w_kvln
    rmsnorm_kernel<<<NTOK, blk>>>(ckv, w_kvln, cln, KVR, KVR + DROPE);
    // 5. kv = c_ln @ Wkvb^T  [4096 x 4096] K=512
    tf32gemm_nt<0><<<dim3((NH * 256) / 128, NTOK / 128), blk>>>(cln, Wkvb, nullptr, kv, NTOK, NH * 256, KVR);
    // 6/7. layouts + rope
    build_qf<<<NTOK, 128>>>(q, pos, qfp);
    build_kf<<<NTOK, 128>>>(kv, ckv, pos, kfp, vp);
    // 8. attention
    attn_kernel<<<dim3(SEQ / 16, NH, BATCH), blk>>>(qfp, kfp, vp, attn);
    // 9. x1 = hidden + attn @ Wo^T  K=2048
    tf32gemm_nt<1><<<dim3(HID / 128, NTOK / 128), blk>>>(attn, Wo, hidden, x1, NTOK, HID, NH * DV);
    // 10. y = rms(x1) * w_ln2
    rmsnorm_kernel<<<NTOK, blk>>>(x1, w_ln2, y, HID, HID);
    // 11. g = y @ Wg^T, u = y @ Wu^T  [4096 x 10944] K=2048
    tf32gemm_nt<0><<<dim3((INTER + 127) / 128, NTOK / 128), blk>>>(y, Wg, nullptr, gg, NTOK, INTER, HID);
    tf32gemm_nt<0><<<dim3((INTER + 127) / 128, NTOK / 128), blk>>>(y, Wu, nullptr, uu, NTOK, INTER, HID);
    // 12. g = silu(g) * u
    silu_mul<<<4096, blk>>>(gg, uu, (size_t)NTOK * INTER);
    // 13. out = x1 + g @ Wd^T  K=10944
    tf32gemm_nt<1><<<dim3(HID / 128, NTOK / 128), blk>>>(gg, Wd, x1, out, NTOK, HID, INTER);
}